// round 3
// baseline (speedup 1.0000x reference)
#include <cuda_runtime.h>

#define NBATCH 32
#define NN 1024
#define NROWS (NBATCH * NN)        // 32768 output rows
#define ROWS_PER_EXP 16            // rows zero-filled+patched per expander block
#define EXP_BLOCKS (NROWS / ROWS_PER_EXP)   // 2048

// persistent device scratch (no allocations allowed)
__device__ float    g_ranks[NROWS];
__device__ unsigned g_flag[NBATCH];   // zero-init
__device__ unsigned g_epoch;          // zero-init

__global__ void bump_epoch() { g_epoch = g_epoch + 1; }

// ---------------------------------------------------------------------------
// Fused kernel.
//  blocks [0, 32):    per-batch-row sort (u64-key bitonic, 1 barrier/stage)
//                     + chunked PAV + serial merge + rank scatter + flag release
//  blocks [32, 2080): zero-fill own 64KB chunk of out (independent of ranks),
//                     then wait for this batch's flag and patch the <=2
//                     nonzero cells per row.
// ---------------------------------------------------------------------------
__global__ void __launch_bounds__(NN) fused_kernel(const float* __restrict__ x,
                                                   float* __restrict__ out) {
    const int t = threadIdx.x;
    const unsigned ep = g_epoch;

    if (blockIdx.x < NBATCH) {
        // ======================= sorter block =======================
        __shared__ unsigned long long sA[NN];   // ping
        __shared__ unsigned long long sB[NN];   // pong
        __shared__ float thv[NN];               // original theta by index
        __shared__ float ysw[33 * 32];          // y, swizzled (idx -> (idx%32)*... see below)
        __shared__ float cm[33 * 32];           // chunk PAV stacks: means
        __shared__ int   cc[33 * 32];           // chunk PAV stacks: counts
        __shared__ int   bn[32];                // blocks per chunk
        __shared__ float fm[NN];                // final block means
        __shared__ int   fc[NN];                // final block counts
        __shared__ int   fs[NN + 1];            // final block starts
        __shared__ int   nbF;

        const int b = blockIdx.x;
        float v = x[b * NN + t];                // eps = 1.0 -> theta = x
        thv[t] = v;

        // 64-bit sort key: ascending sort == descending by value, ties by index asc.
        unsigned u  = __float_as_uint(v);
        unsigned ka = u ^ ((u & 0x80000000u) ? 0xFFFFFFFFu : 0x80000000u); // asc float order
        unsigned long long cur =
            ((unsigned long long)(~ka) << 32) | (unsigned)t;

        // ---- bitonic sort (ascending), hybrid shared/shfl ----
        int pp = 0;
        for (int k = 2; k <= NN; k <<= 1) {
            const bool asc = ((t & k) == 0);
            for (int j = k >> 1; j >= 32; j >>= 1) {
                unsigned long long* buf = pp ? sB : sA;
                buf[t] = cur;
                __syncthreads();
                unsigned long long other = buf[t ^ j];
                pp ^= 1;
                bool takeMin = (((t & j) == 0) == asc);
                cur = takeMin ? (cur < other ? cur : other)
                              : (cur > other ? cur : other);
            }
            int j0 = (k >> 1) < 16 ? (k >> 1) : 16;
            for (int j = j0; j >= 1; j >>= 1) {
                unsigned long long other = __shfl_xor_sync(0xFFFFFFFFu, cur, j);
                bool takeMin = (((t & j) == 0) == asc);
                cur = takeMin ? (cur < other ? cur : other)
                              : (cur > other ? cur : other);
            }
        }

        // thread t now holds sorted position t; recover id and value
        const int   id  = (int)(cur & 0xFFFFFFFFull);
        const float s_t = thv[id];

        // y[t] = s_t - (NN - t), stored swizzled so chunk-PAV reads are
        // conflict-free: logical idx q stored at (q%32)*33 + q/32... i.e. for
        // reader lane l, element i: addr = i*33 + l.
        ysw[(t & 31) * 33 + (t >> 5)] = s_t - (float)(NN - t);
        __syncthreads();

        // ---- chunked PAV: warp 0, lane l handles y[32l .. 32l+31] ----
        if (t < 32) {
            int   nb = 0;
            float tm = ysw[t];          // i = 0 -> addr 0*33 + t
            int   tc = 1;
            for (int i = 1; i < 32; i++) {
                float m = ysw[i * 33 + t];
                int   c = 1;
                while (tc > 0 && tm < m) {          // merge on violation
                    m = (tm * (float)tc + m * (float)c) / (float)(tc + c);
                    c += tc;
                    if (nb == 0) { tc = 0; break; }
                    nb--; tm = cm[nb * 33 + t]; tc = cc[nb * 33 + t];
                }
                if (tc > 0) { cm[nb * 33 + t] = tm; cc[nb * 33 + t] = tc; nb++; }
                tm = m; tc = c;
            }
            cm[nb * 33 + t] = tm; cc[nb * 33 + t] = tc; nb++;
            bn[t] = nb;
        }
        __syncthreads();

        // ---- serial merge of the 32 chunk stacks (short: data nearly merges) ----
        if (t == 0) {
            int   nb = 0;
            float tm = 0.0f;
            int   tc = 0;
            for (int l = 0; l < 32; l++) {
                const int cnt = bn[l];
                for (int i = 0; i < cnt; i++) {
                    float m = cm[i * 33 + l];
                    int   c = cc[i * 33 + l];
                    if (tc == 0) { tm = m; tc = c; continue; }
                    while (tc > 0 && tm < m) {
                        m = (tm * (float)tc + m * (float)c) / (float)(tc + c);
                        c += tc;
                        if (nb == 0) { tc = 0; break; }
                        nb--; tm = fm[nb]; tc = fc[nb];
                    }
                    if (tc > 0) { fm[nb] = tm; fc[nb] = tc; nb++; }
                    tm = m; tc = c;
                }
            }
            fm[nb] = tm; fc[nb] = tc; nb++;
            int pos = 0;
            for (int q = 0; q < nb; q++) { fs[q] = pos; pos += fc[q]; }
            fs[nb] = pos;
            nbF = nb;
        }
        __syncthreads();

        // ---- expand sol via binary search, scatter rank through permutation ----
        {
            int lo = 0, hi = nbF - 1;
            while (lo < hi) {
                int mid = (lo + hi + 1) >> 1;
                if (fs[mid] <= t) lo = mid; else hi = mid - 1;
            }
            g_ranks[b * NN + id] = s_t - fm[lo];
        }
        __syncthreads();
        if (t == 0) {
            __threadfence();
            atomicExch(&g_flag[b], ep);   // release: ranks for batch b ready
        }
    } else {
        // ======================= expander block =======================
        const int e = blockIdx.x - NBATCH;          // 0 .. EXP_BLOCKS-1

        // Phase 1: zero-fill own 64KB chunk (independent of ranks).
        float4* out4 = (float4*)out + (size_t)e * 4096;
        const float4 z = make_float4(0.0f, 0.0f, 0.0f, 0.0f);
        out4[t]        = z;
        out4[t + 1024] = z;
        out4[t + 2048] = z;
        out4[t + 3072] = z;
        __syncthreads();

        // Phase 2: wait for this batch's ranks, then patch nonzero band.
        const int R0 = e * ROWS_PER_EXP;            // first global row
        const int b  = R0 >> 10;                    // same batch for all 16 rows
        if (t == 0) {
            while (atomicAdd(&g_flag[b], 0u) != ep) __nanosleep(64);
            __threadfence();
        }
        __syncthreads();

        if (t < ROWS_PER_EXP) {
            const int   R = R0 + t;
            const float r = g_ranks[R];
            const int  t0 = (int)floorf(r);
            #pragma unroll
            for (int d = 0; d <= 1; d++) {
                int tt = t0 + d;                    // candidate target (i+1)
                if (tt >= 1 && tt <= NN) {
                    float val = 1.0f - fabsf(r - (float)tt);
                    if (val > 0.0f)
                        out[(size_t)R * NN + (tt - 1)] = val;
                }
            }
        }
    }
}

extern "C" void kernel_launch(void* const* d_in, const int* in_sizes, int n_in,
                              void* d_out, int out_size) {
    const float* x = (const float*)d_in[0];
    bump_epoch<<<1, 1>>>();
    fused_kernel<<<NBATCH + EXP_BLOCKS, NN>>>(x, (float*)d_out);
}

// round 5
// speedup vs baseline: 1.4687x; 1.4687x over previous
#include <cuda_runtime.h>

#define NBATCH 32
#define NN 1024
#define NROWS (NBATCH * NN)          // 32768 output rows
#define ROWS_PER_EXP 16              // rows per expander chunk (64KB)
#define EXP_BLOCKS (NROWS / ROWS_PER_EXP)     // 2048
#define CHUNKS_PER_BATCH (NN / ROWS_PER_EXP)  // 64

// persistent device scratch (zero-initialized at load; counters accumulate
// across graph replays, compared against epoch-scaled targets)
__device__ unsigned g_fill[NBATCH];
__device__ unsigned g_epoch;

__global__ void bump_epoch() { g_epoch = g_epoch + 1; }

// ---------------------------------------------------------------------------
// Fused kernel.
//  blocks [0, 32):    sorter/patcher per batch: u64-key bitonic sort, chunked
//                     PAV, then WAIT for this batch's 64 fill chunks and
//                     scatter the <=2 nonzero floats per row.
//  blocks [32, 2080): pure zero-fill of one 64KB chunk; fence; count; exit.
//                     Never waits -> uninterrupted DRAM stream.
// ---------------------------------------------------------------------------
__global__ void __launch_bounds__(NN) fused_kernel(const float* __restrict__ x,
                                                   float* __restrict__ out) {
    const int t = threadIdx.x;
    const unsigned ep = g_epoch;

    if (blockIdx.x >= NBATCH) {
        // ======================= expander block (no waiting) ================
        const int e = blockIdx.x - NBATCH;           // 0 .. EXP_BLOCKS-1
        float4* out4 = (float4*)out + (size_t)e * 4096;
        const float4 z = make_float4(0.0f, 0.0f, 0.0f, 0.0f);
        __stcs(out4 + t,        z);
        __stcs(out4 + t + 1024, z);
        __stcs(out4 + t + 2048, z);
        __stcs(out4 + t + 3072, z);
        __syncthreads();
        if (t == 0) {
            __threadfence();
            atomicAdd(&g_fill[e / CHUNKS_PER_BATCH], 1u);
        }
        return;
    }

    // ======================= sorter + patcher block =========================
    __shared__ unsigned long long sA[NN];   // ping
    __shared__ unsigned long long sB[NN];   // pong
    __shared__ float thv[NN];               // original theta by index
    __shared__ float ysw[33 * 32];          // y, swizzled for conflict-free PAV
    __shared__ float cm[33 * 32];           // chunk PAV stacks: means
    __shared__ int   cc[33 * 32];           // chunk PAV stacks: counts
    __shared__ int   bn[32];                // blocks per chunk
    __shared__ float fm[NN];                // final block means
    __shared__ int   fc[NN];                // final block counts
    __shared__ int   fs[NN + 1];            // final block starts
    __shared__ int   nbF;

    const int b = blockIdx.x;
    float v = x[b * NN + t];                // eps = 1.0 -> theta = x
    thv[t] = v;

    // 64-bit key: ascending sort == descending by value, ties by index asc.
    unsigned u  = __float_as_uint(v);
    unsigned ka = u ^ ((u & 0x80000000u) ? 0xFFFFFFFFu : 0x80000000u);
    unsigned long long cur = ((unsigned long long)(~ka) << 32) | (unsigned)t;

    // ---- bitonic sort (ascending keys), 1 barrier per shared stage ----
    int pp = 0;
    for (int k = 2; k <= NN; k <<= 1) {
        const bool asc = ((t & k) == 0);
        for (int j = k >> 1; j >= 32; j >>= 1) {
            unsigned long long* buf = pp ? sB : sA;
            buf[t] = cur;
            __syncthreads();
            unsigned long long other = buf[t ^ j];
            pp ^= 1;
            bool takeMin = (((t & j) == 0) == asc);
            cur = takeMin ? (cur < other ? cur : other)
                          : (cur > other ? cur : other);
        }
        int j0 = (k >> 1) < 16 ? (k >> 1) : 16;
        for (int j = j0; j >= 1; j >>= 1) {
            unsigned long long other = __shfl_xor_sync(0xFFFFFFFFu, cur, j);
            bool takeMin = (((t & j) == 0) == asc);
            cur = takeMin ? (cur < other ? cur : other)
                          : (cur > other ? cur : other);
        }
    }

    const int   id  = (int)(cur & 0xFFFFFFFFull);   // original index at rank t
    const float s_t = thv[id];                      // sorted (descending) value

    // y[t] = s_t - (NN - t), swizzled: reader lane l, elem i -> addr i*33 + l
    ysw[(t & 31) * 33 + (t >> 5)] = s_t - (float)(NN - t);
    __syncthreads();

    // ---- chunked PAV: warp 0, lane l handles y[32l .. 32l+31] ----
    if (t < 32) {
        int   nb = 0;
        float tm = ysw[t];
        int   tc = 1;
        for (int i = 1; i < 32; i++) {
            float m = ysw[i * 33 + t];
            int   c = 1;
            while (tc > 0 && tm < m) {
                m = (tm * (float)tc + m * (float)c) / (float)(tc + c);
                c += tc;
                if (nb == 0) { tc = 0; break; }
                nb--; tm = cm[nb * 33 + t]; tc = cc[nb * 33 + t];
            }
            if (tc > 0) { cm[nb * 33 + t] = tm; cc[nb * 33 + t] = tc; nb++; }
            tm = m; tc = c;
        }
        cm[nb * 33 + t] = tm; cc[nb * 33 + t] = tc; nb++;
        bn[t] = nb;
    }
    __syncthreads();

    // ---- serial merge of the 32 chunk stacks (short) ----
    if (t == 0) {
        int   nb = 0;
        float tm = 0.0f;
        int   tc = 0;
        for (int l = 0; l < 32; l++) {
            const int cnt = bn[l];
            for (int i = 0; i < cnt; i++) {
                float m = cm[i * 33 + l];
                int   c = cc[i * 33 + l];
                if (tc == 0) { tm = m; tc = c; continue; }
                while (tc > 0 && tm < m) {
                    m = (tm * (float)tc + m * (float)c) / (float)(tc + c);
                    c += tc;
                    if (nb == 0) { tc = 0; break; }
                    nb--; tm = fm[nb]; tc = fc[nb];
                }
                if (tc > 0) { fm[nb] = tm; fc[nb] = tc; nb++; }
                tm = m; tc = c;
            }
        }
        fm[nb] = tm; fc[nb] = tc; nb++;
        int pos = 0;
        for (int q = 0; q < nb; q++) { fs[q] = pos; pos += fc[q]; }
        fs[nb] = pos;
        nbF = nb;
    }
    __syncthreads();

    // ---- rank for original row `id`: primal = s - sol ----
    float r;
    {
        int lo = 0, hi = nbF - 1;
        while (lo < hi) {
            int mid = (lo + hi + 1) >> 1;
            if (fs[mid] <= t) lo = mid; else hi = mid - 1;
        }
        r = s_t - fm[lo];
    }

    // ---- wait for this batch's 64 zero-fill chunks, then patch ----
    if (t == 0) {
        const unsigned target = ep * (unsigned)CHUNKS_PER_BATCH;
        while (atomicAdd(&g_fill[b], 0u) != target) __nanosleep(128);
        __threadfence();   // acquire: fills visible before our patch stores
    }
    __syncthreads();

    {
        const size_t rowBase = ((size_t)b * NN + (size_t)id) * NN;
        const int t0 = (int)floorf(r);
        #pragma unroll
        for (int d = 0; d <= 1; d++) {
            int tt = t0 + d;                 // candidate target (i+1)
            if (tt >= 1 && tt <= NN) {
                float val = 1.0f - fabsf(r - (float)tt);
                if (val > 0.0f) out[rowBase + (tt - 1)] = val;
            }
        }
    }
}

extern "C" void kernel_launch(void* const* d_in, const int* in_sizes, int n_in,
                              void* d_out, int out_size) {
    const float* x = (const float*)d_in[0];
    bump_epoch<<<1, 1>>>();
    fused_kernel<<<NBATCH + EXP_BLOCKS, NN>>>(x, (float*)d_out);
}

// round 6
// speedup vs baseline: 1.5137x; 1.0307x over previous
#include <cuda_runtime.h>

#define NBATCH 32
#define NN 1024
#define NROWS (NBATCH * NN)          // 32768 output rows
#define ROWS_PER_EXP 16              // rows per expander chunk (64KB)
#define EXP_BLOCKS (NROWS / ROWS_PER_EXP)     // 2048
#define CHUNKS_PER_BATCH (NN / ROWS_PER_EXP)  // 64

// persistent device scratch (zero-init at load). Self-resetting: each kernel
// invocation raises each counter to 64, the sorter consumes and subtracts 64,
// so every invocation starts from 0. Deterministic across graph replays.
__device__ unsigned g_fill[NBATCH];

// ---------------------------------------------------------------------------
// Fused kernel (single launch).
//  blocks [0, 32):    sorter/patcher per batch: u64-key bitonic sort, chunked
//                     PAV, then wait for this batch's 64 fill chunks and
//                     scatter the <=2 nonzero floats per row.
//  blocks [32, 2080): pure zero-fill of one 64KB chunk via write-through
//                     stores; fence; count; exit. Never waits.
// ---------------------------------------------------------------------------
__global__ void __launch_bounds__(NN) fused_kernel(const float* __restrict__ x,
                                                   float* __restrict__ out) {
    const int t = threadIdx.x;

    if (blockIdx.x >= NBATCH) {
        // ======================= expander block (no waiting) ================
        const int e = blockIdx.x - NBATCH;           // 0 .. EXP_BLOCKS-1
        float4* out4 = (float4*)out + (size_t)e * 4096;
        const float4 z = make_float4(0.0f, 0.0f, 0.0f, 0.0f);
        __stwt(out4 + t,        z);
        __stwt(out4 + t + 1024, z);
        __stwt(out4 + t + 2048, z);
        __stwt(out4 + t + 3072, z);
        __syncthreads();
        if (t == 0) {
            __threadfence();
            atomicAdd(&g_fill[e / CHUNKS_PER_BATCH], 1u);
        }
        return;
    }

    // ======================= sorter + patcher block =========================
    __shared__ unsigned long long sA[NN];   // ping
    __shared__ unsigned long long sB[NN];   // pong
    __shared__ float thv[NN];               // original theta by index
    __shared__ float ysw[33 * 32];          // y, swizzled for conflict-free PAV
    __shared__ float cm[33 * 32];           // chunk PAV stacks: means
    __shared__ int   cc[33 * 32];           // chunk PAV stacks: counts
    __shared__ int   bn[32];                // blocks per chunk
    __shared__ float fm[NN];                // final block means
    __shared__ int   fc[NN];                // final block counts
    __shared__ int   fs[NN + 1];            // final block starts
    __shared__ int   nbF;

    const int b = blockIdx.x;
    float v = x[b * NN + t];                // eps = 1.0 -> theta = x
    thv[t] = v;

    // 64-bit key: ascending sort == descending by value, ties by index asc.
    unsigned u  = __float_as_uint(v);
    unsigned ka = u ^ ((u & 0x80000000u) ? 0xFFFFFFFFu : 0x80000000u);
    unsigned long long cur = ((unsigned long long)(~ka) << 32) | (unsigned)t;

    // ---- bitonic sort (ascending keys), 1 barrier per shared stage ----
    int pp = 0;
    for (int k = 2; k <= NN; k <<= 1) {
        const bool asc = ((t & k) == 0);
        for (int j = k >> 1; j >= 32; j >>= 1) {
            unsigned long long* buf = pp ? sB : sA;
            buf[t] = cur;
            __syncthreads();
            unsigned long long other = buf[t ^ j];
            pp ^= 1;
            bool takeMin = (((t & j) == 0) == asc);
            cur = takeMin ? (cur < other ? cur : other)
                          : (cur > other ? cur : other);
        }
        int j0 = (k >> 1) < 16 ? (k >> 1) : 16;
        for (int j = j0; j >= 1; j >>= 1) {
            unsigned long long other = __shfl_xor_sync(0xFFFFFFFFu, cur, j);
            bool takeMin = (((t & j) == 0) == asc);
            cur = takeMin ? (cur < other ? cur : other)
                          : (cur > other ? cur : other);
        }
    }

    const int   id  = (int)(cur & 0xFFFFFFFFull);   // original index at rank t
    const float s_t = thv[id];                      // sorted (descending) value

    // y[t] = s_t - (NN - t), swizzled: reader lane l, elem i -> addr i*33 + l
    ysw[(t & 31) * 33 + (t >> 5)] = s_t - (float)(NN - t);
    __syncthreads();

    // ---- chunked PAV: warp 0, lane l handles y[32l .. 32l+31] ----
    if (t < 32) {
        int   nb = 0;
        float tm = ysw[t];
        int   tc = 1;
        for (int i = 1; i < 32; i++) {
            float m = ysw[i * 33 + t];
            int   c = 1;
            while (tc > 0 && tm < m) {
                m = (tm * (float)tc + m * (float)c) / (float)(tc + c);
                c += tc;
                if (nb == 0) { tc = 0; break; }
                nb--; tm = cm[nb * 33 + t]; tc = cc[nb * 33 + t];
            }
            if (tc > 0) { cm[nb * 33 + t] = tm; cc[nb * 33 + t] = tc; nb++; }
            tm = m; tc = c;
        }
        cm[nb * 33 + t] = tm; cc[nb * 33 + t] = tc; nb++;
        bn[t] = nb;
    }
    __syncthreads();

    // ---- serial merge of the 32 chunk stacks (short) ----
    if (t == 0) {
        int   nb = 0;
        float tm = 0.0f;
        int   tc = 0;
        for (int l = 0; l < 32; l++) {
            const int cnt = bn[l];
            for (int i = 0; i < cnt; i++) {
                float m = cm[i * 33 + l];
                int   c = cc[i * 33 + l];
                if (tc == 0) { tm = m; tc = c; continue; }
                while (tc > 0 && tm < m) {
                    m = (tm * (float)tc + m * (float)c) / (float)(tc + c);
                    c += tc;
                    if (nb == 0) { tc = 0; break; }
                    nb--; tm = fm[nb]; tc = fc[nb];
                }
                if (tc > 0) { fm[nb] = tm; fc[nb] = tc; nb++; }
                tm = m; tc = c;
            }
        }
        fm[nb] = tm; fc[nb] = tc; nb++;
        int pos = 0;
        for (int q = 0; q < nb; q++) { fs[q] = pos; pos += fc[q]; }
        fs[nb] = pos;
        nbF = nb;
    }
    __syncthreads();

    // ---- rank for original row `id`: primal = s - sol ----
    float r;
    {
        int lo = 0, hi = nbF - 1;
        while (lo < hi) {
            int mid = (lo + hi + 1) >> 1;
            if (fs[mid] <= t) lo = mid; else hi = mid - 1;
        }
        r = s_t - fm[lo];
    }

    // ---- wait for this batch's 64 zero-fill chunks, then reset + patch ----
    if (t == 0) {
        while (atomicAdd(&g_fill[b], 0u) < (unsigned)CHUNKS_PER_BATCH)
            __nanosleep(128);
        __threadfence();                         // acquire: fills visible
        atomicSub(&g_fill[b], (unsigned)CHUNKS_PER_BATCH);  // reset for next replay
    }
    __syncthreads();

    {
        const size_t rowBase = ((size_t)b * NN + (size_t)id) * NN;
        const int t0 = (int)floorf(r);
        #pragma unroll
        for (int d = 0; d <= 1; d++) {
            int tt = t0 + d;                 // candidate target (i+1)
            if (tt >= 1 && tt <= NN) {
                float val = 1.0f - fabsf(r - (float)tt);
                if (val > 0.0f) out[rowBase + (tt - 1)] = val;
            }
        }
    }
}

extern "C" void kernel_launch(void* const* d_in, const int* in_sizes, int n_in,
                              void* d_out, int out_size) {
    const float* x = (const float*)d_in[0];
    fused_kernel<<<NBATCH + EXP_BLOCKS, NN>>>(x, (float*)d_out);
}